// round 6
// baseline (speedup 1.0000x reference)
#include <cuda_runtime.h>
#include <cstdint>

#define NPTS    8192
#define GAMMA_  100.0f
#define LOG2E   1.4426950408889634f
#define NCELL   512            // 8x8x8 Morton cells
#define CHUNK   32
#define NCHUNK  (NPTS / CHUNK) // 256
#define JSPLIT  16
#define CPB     (NCHUNK / JSPLIT)  // 16 chunks per CTA split
#define RCUT2   0.16f          // r > 0.4 -> K < 1.2e-7, safe to skip

// ---- device scratch (no allocations allowed) ----
__device__ int    g_cnt[NCELL];
__device__ int    g_off[NCELL];
__device__ int    g_perm[NPTS];
__device__ float4 g_sx[NPTS];        // sorted: (xt0, xt1, xt2, s2j)
__device__ float4 g_sp[NPTS];        // sorted: (p0, p1, p2, 0)
__device__ float4 g_bb[NCHUNK * 2];  // per chunk: [2c]=min, [2c+1]=max

__device__ __forceinline__ int spread3(int v) {   // 3 bits -> positions 0,3,6
    return (v & 1) | ((v & 2) << 2) | ((v & 4) << 4);
}
__device__ __forceinline__ int cell_of(float x0, float x1, float x2) {
    int cx = min(7, max(0, (int)(x0 * 8.0f)));
    int cy = min(7, max(0, (int)(x1 * 8.0f)));
    int cz = min(7, max(0, (int)(x2 * 8.0f)));
    return spread3(cx) | (spread3(cy) << 1) | (spread3(cz) << 2);
}

// K0: zero output + cell counts
__global__ void k_zero(float* __restrict__ out, int n) {
    int i = blockIdx.x * blockDim.x + threadIdx.x;
    if (i < n) out[i] = 0.0f;
    else if (i < n + NCELL) g_cnt[i - n] = 0;
}

// K1: histogram
__global__ void k_hist(const float* __restrict__ x) {
    int i = blockIdx.x * blockDim.x + threadIdx.x;
    if (i >= NPTS) return;
    atomicAdd(&g_cnt[cell_of(x[3*i], x[3*i+1], x[3*i+2])], 1);
}

// K2: exclusive prefix sum over 512 cells (1 CTA)
__global__ void k_scan() {
    __shared__ int s[NCELL];
    int t = threadIdx.x;
    int v0 = g_cnt[t];
    s[t] = v0;
    __syncthreads();
    for (int d = 1; d < NCELL; d <<= 1) {
        int v = (t >= d) ? s[t - d] : 0;
        __syncthreads();
        s[t] += v;
        __syncthreads();
    }
    g_off[t] = s[t] - v0;
}

// K3: scatter into sorted order (recentred coords + exp bias in .w)
__global__ void k_scatter(const float* __restrict__ mom, const float* __restrict__ x) {
    int i = blockIdx.x * blockDim.x + threadIdx.x;
    if (i >= NPTS) return;
    const float a0 = x[3*i] - 0.5f, a1 = x[3*i+1] - 0.5f, a2 = x[3*i+2] - 0.5f;
    const int c = cell_of(x[3*i], x[3*i+1], x[3*i+2]);
    const int slot = atomicAdd(&g_off[c], 1);
    const float s2 = -GAMMA_ * LOG2E * (a0*a0 + a1*a1 + a2*a2);
    g_perm[slot] = i;
    g_sx[slot] = make_float4(a0, a1, a2, s2);
    g_sp[slot] = make_float4(mom[3*i], mom[3*i+1], mom[3*i+2], 0.0f);
}

// K4: per-chunk AABB (256 threads, one chunk each)
__global__ void k_bb() {
    int c = threadIdx.x;
    float4 mn = make_float4( 1e9f,  1e9f,  1e9f, 0.f);
    float4 mx = make_float4(-1e9f, -1e9f, -1e9f, 0.f);
    #pragma unroll 4
    for (int k = 0; k < CHUNK; k++) {
        float4 v = g_sx[c * CHUNK + k];
        mn.x = fminf(mn.x, v.x); mx.x = fmaxf(mx.x, v.x);
        mn.y = fminf(mn.y, v.y); mx.y = fmaxf(mx.y, v.y);
        mn.z = fminf(mn.z, v.z); mx.z = fmaxf(mx.z, v.z);
    }
    g_bb[2*c]   = mn;
    g_bb[2*c+1] = mx;
}

// K5: main O(N^2) with warp-level chunk culling
__global__ __launch_bounds__(256)
void lddmm_main(float* __restrict__ out)
{
    const int tid = threadIdx.x;
    const int i   = blockIdx.x * 256 + tid;

    const float4 XI = g_sx[i];
    const float4 PI = g_sp[i];

    // warp AABB over lanes' i-points (warp-uniform after reduce)
    float mnx = XI.x, mxx = XI.x, mny = XI.y, mxy = XI.y, mnz = XI.z, mxz = XI.z;
    #pragma unroll
    for (int s = 16; s; s >>= 1) {
        mnx = fminf(mnx, __shfl_xor_sync(0xffffffffu, mnx, s));
        mxx = fmaxf(mxx, __shfl_xor_sync(0xffffffffu, mxx, s));
        mny = fminf(mny, __shfl_xor_sync(0xffffffffu, mny, s));
        mxy = fmaxf(mxy, __shfl_xor_sync(0xffffffffu, mxy, s));
        mnz = fminf(mnz, __shfl_xor_sync(0xffffffffu, mnz, s));
        mxz = fmaxf(mxz, __shfl_xor_sync(0xffffffffu, mxz, s));
    }

    const float g2l = 2.0f * GAMMA_ * LOG2E;
    const float gx0 = g2l * XI.x, gx1 = g2l * XI.y, gx2 = g2l * XI.z;
    const float aiv = XI.w;                       // = -gamma*log2e*|xt_i|^2

    float dx0 = 0.f, dx1 = 0.f, dx2 = 0.f;        // sum K*pj
    float q0  = 0.f, q1  = 0.f, q2  = 0.f;        // sum w*xt_j

    const int c0 = blockIdx.y * CPB;
    for (int c = c0; c < c0 + CPB; c++) {
        const float4 bmn = g_bb[2*c];
        const float4 bmx = g_bb[2*c+1];
        float ax = fmaxf(fmaxf(bmn.x - mxx, mnx - bmx.x), 0.f);
        float ay = fmaxf(fmaxf(bmn.y - mxy, mny - bmx.y), 0.f);
        float az = fmaxf(fmaxf(bmn.z - mxz, mnz - bmx.z), 0.f);
        const float dist2 = ax*ax + ay*ay + az*az;
        if (dist2 > RCUT2) continue;              // warp-uniform skip

        const float4* __restrict__ xj = &g_sx[c * CHUNK];
        const float4* __restrict__ pj = &g_sp[c * CHUNK];
        #pragma unroll 8
        for (int k = 0; k < CHUNK; k++) {
            const float4 XJ = xj[k];              // warp-uniform LDG, L1-hot
            const float4 PJ = pj[k];

            float arg = fmaf(gx0, XJ.x, XJ.w);
            arg = fmaf(gx1, XJ.y, arg);
            arg = fmaf(gx2, XJ.z, arg);
            arg += aiv;

            float Kv;
            asm("ex2.approx.f32 %0, %1;" : "=f"(Kv) : "f"(arg));

            float pd = PI.x * PJ.x;
            pd = fmaf(PI.y, PJ.y, pd);
            pd = fmaf(PI.z, PJ.z, pd);
            const float w = Kv * pd;

            dx0 = fmaf(Kv, PJ.x, dx0);
            dx1 = fmaf(Kv, PJ.y, dx1);
            dx2 = fmaf(Kv, PJ.z, dx2);
            q0  = fmaf(w, XJ.x, q0);
            q1  = fmaf(w, XJ.y, q1);
            q2  = fmaf(w, XJ.z, q2);
        }
    }

    // ws = sum_j K <pi,pj> = pi . dx   (exact identity)
    const float ws = PI.x * dx0 + PI.y * dx1 + PI.z * dx2;
    const int oi = g_perm[i];
    const float cc = 2.0f * GAMMA_;
    atomicAdd(&out[3*oi + 0], cc * fmaf(XI.x, ws, -q0));
    atomicAdd(&out[3*oi + 1], cc * fmaf(XI.y, ws, -q1));
    atomicAdd(&out[3*oi + 2], cc * fmaf(XI.z, ws, -q2));
    atomicAdd(&out[3*NPTS + 3*oi + 0], dx0);
    atomicAdd(&out[3*NPTS + 3*oi + 1], dx1);
    atomicAdd(&out[3*NPTS + 3*oi + 2], dx2);
}

extern "C" void kernel_launch(void* const* d_in, const int* in_sizes, int n_in,
                              void* d_out, int out_size)
{
    const float* mom = (const float*)d_in[0];   // [1, 8192, 3]
    const float* x   = (const float*)d_in[1];   // [1, 8192, 3]
    float*       out = (float*)d_out;           // [2, 8192, 3] = dmom | dx

    k_zero<<<(out_size + NCELL + 255) / 256, 256>>>(out, out_size);
    k_hist<<<NPTS / 256, 256>>>(x);
    k_scan<<<1, NCELL>>>();
    k_scatter<<<NPTS / 256, 256>>>(mom, x);
    k_bb<<<1, NCHUNK>>>();

    dim3 grid(NPTS / 256, JSPLIT);              // (32, 16) = 512 CTAs
    lddmm_main<<<grid, 256>>>(out);
}

// round 7
// speedup vs baseline: 1.3788x; 1.3788x over previous
#include <cuda_runtime.h>
#include <cstdint>

#define NPTS    8192
#define GAMMA_  100.0f
#define LOG2E   1.4426950408889634f
#define NCELL   512            // 8x8x8 Morton cells
#define CHUNK   32
#define NCHUNK  (NPTS / CHUNK) // 256
#define TILE    256            // j per CTA
#define NSPLIT  (NPTS / TILE)  // 32
#define CPT     (TILE / CHUNK) // 8 chunks per tile
#define RCUT2   0.16f          // r > 0.4 -> K < 1.2e-7, skippable

// ---- device scratch ----
__device__ int    g_perm[NPTS];
__device__ float4 g_sx[NPTS];        // sorted: (xt0, xt1, xt2, s2j)
__device__ float4 g_sp[NPTS];        // sorted: (p0, p1, p2, 0)
__device__ float4 g_bb[NCHUNK * 2];  // per 32-chunk: [2c]=min, [2c+1]=max

__device__ __forceinline__ int spread3(int v) {
    return (v & 1) | ((v & 2) << 2) | ((v & 4) << 4);
}
__device__ __forceinline__ int cell_of(float x0, float x1, float x2) {
    int cx = min(7, max(0, (int)(x0 * 8.0f)));
    int cy = min(7, max(0, (int)(x1 * 8.0f)));
    int cz = min(7, max(0, (int)(x2 * 8.0f)));
    return spread3(cx) | (spread3(cy) << 1) | (spread3(cz) << 2);
}

__global__ void k_zero(float* __restrict__ out, int n) {
    int i = blockIdx.x * blockDim.x + threadIdx.x;
    if (i < n) out[i] = 0.0f;
}

// Fused: histogram -> scan -> scatter -> chunk AABBs. One CTA, 1024 threads.
__global__ __launch_bounds__(1024)
void k_sort(const float* __restrict__ mom, const float* __restrict__ x)
{
    __shared__ int cnt[NCELL];
    __shared__ int scn[NCELL];
    const int t = threadIdx.x;

    if (t < NCELL) cnt[t] = 0;
    __syncthreads();

    int mycell[8];
    #pragma unroll
    for (int r = 0; r < 8; r++) {
        const int i = r * 1024 + t;
        const int c = cell_of(x[3*i], x[3*i+1], x[3*i+2]);
        mycell[r] = c;
        atomicAdd(&cnt[c], 1);
    }
    __syncthreads();

    if (t < NCELL) scn[t] = cnt[t];
    __syncthreads();
    for (int d = 1; d < NCELL; d <<= 1) {
        int v = (t >= d && t < NCELL) ? scn[t - d] : 0;
        __syncthreads();
        if (t < NCELL) scn[t] += v;
        __syncthreads();
    }
    if (t < NCELL) cnt[t] = scn[t] - cnt[t];   // exclusive base, bumped below
    __syncthreads();

    #pragma unroll
    for (int r = 0; r < 8; r++) {
        const int i = r * 1024 + t;
        const float a0 = x[3*i] - 0.5f, a1 = x[3*i+1] - 0.5f, a2 = x[3*i+2] - 0.5f;
        const int slot = atomicAdd(&cnt[mycell[r]], 1);
        const float s2 = -GAMMA_ * LOG2E * (a0*a0 + a1*a1 + a2*a2);
        g_perm[slot] = i;
        g_sx[slot] = make_float4(a0, a1, a2, s2);
        g_sp[slot] = make_float4(mom[3*i], mom[3*i+1], mom[3*i+2], 0.0f);
    }
    __syncthreads();

    if (t < NCHUNK) {
        float4 mn = make_float4( 1e9f,  1e9f,  1e9f, 0.f);
        float4 mx = make_float4(-1e9f, -1e9f, -1e9f, 0.f);
        #pragma unroll 4
        for (int k = 0; k < CHUNK; k++) {
            const float4 v = g_sx[t * CHUNK + k];
            mn.x = fminf(mn.x, v.x); mx.x = fmaxf(mx.x, v.x);
            mn.y = fminf(mn.y, v.y); mx.y = fmaxf(mx.y, v.y);
            mn.z = fminf(mn.z, v.z); mx.z = fmaxf(mx.z, v.z);
        }
        g_bb[2*t]   = mn;
        g_bb[2*t+1] = mx;
    }
}

__device__ __forceinline__ float boxdist2(float4 amn, float4 amx, float4 bmn, float4 bmx) {
    const float ax = fmaxf(fmaxf(bmn.x - amx.x, amn.x - bmx.x), 0.f);
    const float ay = fmaxf(fmaxf(bmn.y - amx.y, amn.y - bmx.y), 0.f);
    const float az = fmaxf(fmaxf(bmn.z - amx.z, amn.z - bmx.z), 0.f);
    return ax*ax + ay*ay + az*az;
}

__global__ __launch_bounds__(256)
void lddmm_main(float* __restrict__ out)
{
    __shared__ float4 sA[TILE];
    __shared__ float4 sB[TILE];
    __shared__ float4 cbb[CPT * 2];
    __shared__ float4 wbb[8 * 2];

    const int tid = threadIdx.x;
    const int wid = tid >> 5;
    const int i   = blockIdx.x * 256 + tid;

    const float4 XI = g_sx[i];
    const float4 PI = g_sp[i];

    // warp AABB over lanes' i-points
    float mnx = XI.x, mxx = XI.x, mny = XI.y, mxy = XI.y, mnz = XI.z, mxz = XI.z;
    #pragma unroll
    for (int s = 16; s; s >>= 1) {
        mnx = fminf(mnx, __shfl_xor_sync(0xffffffffu, mnx, s));
        mxx = fmaxf(mxx, __shfl_xor_sync(0xffffffffu, mxx, s));
        mny = fminf(mny, __shfl_xor_sync(0xffffffffu, mny, s));
        mxy = fmaxf(mxy, __shfl_xor_sync(0xffffffffu, mxy, s));
        mnz = fminf(mnz, __shfl_xor_sync(0xffffffffu, mnz, s));
        mxz = fmaxf(mxz, __shfl_xor_sync(0xffffffffu, mxz, s));
    }
    if ((tid & 31) == 0) {
        wbb[2*wid]   = make_float4(mnx, mny, mnz, 0.f);
        wbb[2*wid+1] = make_float4(mxx, mxy, mxz, 0.f);
    }

    const int cbase = blockIdx.y * CPT;
    if (tid < CPT * 2) cbb[tid] = g_bb[cbase * 2 + tid];
    __syncthreads();

    // block AABB + tile AABB -> CTA-level cull before loading the tile
    float4 bmn = wbb[0], bmx = wbb[1];
    #pragma unroll
    for (int w = 1; w < 8; w++) {
        const float4 a = wbb[2*w], b = wbb[2*w+1];
        bmn.x = fminf(bmn.x, a.x); bmx.x = fmaxf(bmx.x, b.x);
        bmn.y = fminf(bmn.y, a.y); bmx.y = fmaxf(bmx.y, b.y);
        bmn.z = fminf(bmn.z, a.z); bmx.z = fmaxf(bmx.z, b.z);
    }
    float4 tmn = cbb[0], tmx = cbb[1];
    #pragma unroll
    for (int c = 1; c < CPT; c++) {
        const float4 a = cbb[2*c], b = cbb[2*c+1];
        tmn.x = fminf(tmn.x, a.x); tmx.x = fmaxf(tmx.x, b.x);
        tmn.y = fminf(tmn.y, a.y); tmx.y = fmaxf(tmx.y, b.y);
        tmn.z = fminf(tmn.z, a.z); tmx.z = fmaxf(tmx.z, b.z);
    }
    if (boxdist2(bmn, bmx, tmn, tmx) > RCUT2) return;   // block-uniform

    // load j-tile into smem
    {
        const int j = blockIdx.y * TILE + tid;
        sA[tid] = g_sx[j];
        sB[tid] = g_sp[j];
    }
    __syncthreads();

    const float g2l = 2.0f * GAMMA_ * LOG2E;
    const float gx0 = g2l * XI.x, gx1 = g2l * XI.y, gx2 = g2l * XI.z;
    const float aiv = XI.w;

    float dx0 = 0.f, dx1 = 0.f, dx2 = 0.f;
    float q0  = 0.f, q1  = 0.f, q2  = 0.f;

    const float4 wmn = make_float4(mnx, mny, mnz, 0.f);
    const float4 wmx = make_float4(mxx, mxy, mxz, 0.f);

    for (int c = 0; c < CPT; c++) {
        if (boxdist2(wmn, wmx, cbb[2*c], cbb[2*c+1]) > RCUT2) continue;  // warp-uniform

        const int base = c * CHUNK;
        #pragma unroll
        for (int k = 0; k < CHUNK; k++) {
            const float4 XJ = sA[base + k];        // LDS.128 broadcast
            const float4 PJ = sB[base + k];

            float arg = fmaf(gx0, XJ.x, XJ.w);
            arg = fmaf(gx1, XJ.y, arg);
            arg = fmaf(gx2, XJ.z, arg);
            arg += aiv;

            float Kv;
            asm("ex2.approx.f32 %0, %1;" : "=f"(Kv) : "f"(arg));

            float pd = PI.x * PJ.x;
            pd = fmaf(PI.y, PJ.y, pd);
            pd = fmaf(PI.z, PJ.z, pd);
            const float w = Kv * pd;

            dx0 = fmaf(Kv, PJ.x, dx0);
            dx1 = fmaf(Kv, PJ.y, dx1);
            dx2 = fmaf(Kv, PJ.z, dx2);
            q0  = fmaf(w, XJ.x, q0);
            q1  = fmaf(w, XJ.y, q1);
            q2  = fmaf(w, XJ.z, q2);
        }
    }

    // ws = sum_j K <pi,pj> = pi . dx
    const float ws = PI.x * dx0 + PI.y * dx1 + PI.z * dx2;
    const int oi = g_perm[i];
    const float cc = 2.0f * GAMMA_;
    atomicAdd(&out[3*oi + 0], cc * fmaf(XI.x, ws, -q0));
    atomicAdd(&out[3*oi + 1], cc * fmaf(XI.y, ws, -q1));
    atomicAdd(&out[3*oi + 2], cc * fmaf(XI.z, ws, -q2));
    atomicAdd(&out[3*NPTS + 3*oi + 0], dx0);
    atomicAdd(&out[3*NPTS + 3*oi + 1], dx1);
    atomicAdd(&out[3*NPTS + 3*oi + 2], dx2);
}

extern "C" void kernel_launch(void* const* d_in, const int* in_sizes, int n_in,
                              void* d_out, int out_size)
{
    const float* mom = (const float*)d_in[0];   // [1, 8192, 3]
    const float* x   = (const float*)d_in[1];   // [1, 8192, 3]
    float*       out = (float*)d_out;           // [2, 8192, 3] = dmom | dx

    k_zero<<<(out_size + 255) / 256, 256>>>(out, out_size);
    k_sort<<<1, 1024>>>(mom, x);

    dim3 grid(NPTS / 256, NSPLIT);              // (32, 32) = 1024 CTAs
    lddmm_main<<<grid, 256>>>(out);
}

// round 8
// speedup vs baseline: 1.8762x; 1.3608x over previous
#include <cuda_runtime.h>

#define NPTS   8192
#define TILE   256
#define NSPLIT 32              // JCHUNK == TILE == 256
#define GAMMA_ 100.0f          // 1 / sigma^2, sigma = 0.1
#define LOG2E  1.4426950408889634f

__global__ void zero_kernel(float* __restrict__ out, int n) {
    int i = blockIdx.x * blockDim.x + threadIdx.x;
    if (i < n) out[i] = 0.0f;
}

// smem per j (recentered coords): A = (xt0, xt1, xt2, s2j), s2j = -g*l*|xt_j|^2
//                                  B = (pj0, pj1, pj2, 0)
__global__ __launch_bounds__(TILE)
void lddmm_kernel(const float* __restrict__ mom,
                  const float* __restrict__ x,
                  float* __restrict__ out)
{
    __shared__ float4 sA[TILE];
    __shared__ float4 sB[TILE];

    const int tid   = threadIdx.x;
    const int i     = blockIdx.x * TILE + tid;
    const int jbase = blockIdx.y * TILE;

    // ---- fill tile ----
    {
        const int j = jbase + tid;
        const float a0 = x[3*j] - 0.5f, a1 = x[3*j+1] - 0.5f, a2 = x[3*j+2] - 0.5f;
        const float s2 = -GAMMA_ * LOG2E * (a0*a0 + a1*a1 + a2*a2);
        sA[tid] = make_float4(a0, a1, a2, s2);
        sB[tid] = make_float4(mom[3*j], mom[3*j+1], mom[3*j+2], 0.f);
    }

    // ---- per-i loop invariants (recentered) ----
    const float xt0 = x[3*i] - 0.5f, xt1 = x[3*i+1] - 0.5f, xt2 = x[3*i+2] - 0.5f;
    const float pi0 = mom[3*i], pi1 = mom[3*i+1], pi2 = mom[3*i+2];
    const float g2l = 2.0f * GAMMA_ * LOG2E;
    const float gx0 = g2l * xt0, gx1 = g2l * xt1, gx2 = g2l * xt2;
    const float aiv = -GAMMA_ * LOG2E * (xt0*xt0 + xt1*xt1 + xt2*xt2);

    // accumulate with E = 2^(s2j + gx.xj) = K / Ci,  Ci = 2^aiv  (exact factoring)
    float dx0 = 0.f, dx1 = 0.f, dx2 = 0.f;   // sum E*pj
    float q0  = 0.f, q1  = 0.f, q2  = 0.f;   // sum E*pd*xt_j

    __syncthreads();

    #pragma unroll 8
    for (int k = 0; k < TILE; k++) {
        const float4 XJ = sA[k];             // LDS.128 broadcast
        const float4 PJ = sB[k];

        float arg = fmaf(gx0, XJ.x, XJ.w);   // 3 FFMA, no bias add
        arg = fmaf(gx1, XJ.y, arg);
        arg = fmaf(gx2, XJ.z, arg);

        float Ev;
        asm("ex2.approx.f32 %0, %1;" : "=f"(Ev) : "f"(arg));

        float pd = pi0 * PJ.x;
        pd = fmaf(pi1, PJ.y, pd);
        pd = fmaf(pi2, PJ.z, pd);
        const float w = Ev * pd;

        dx0 = fmaf(Ev, PJ.x, dx0);
        dx1 = fmaf(Ev, PJ.y, dx1);
        dx2 = fmaf(Ev, PJ.z, dx2);
        q0  = fmaf(w, XJ.x, q0);
        q1  = fmaf(w, XJ.y, q1);
        q2  = fmaf(w, XJ.z, q2);
    }

    // ---- epilogue: rescale by Ci, finalize, combine across splits ----
    const float Ci = exp2f(aiv);
    const float DX0 = Ci * dx0, DX1 = Ci * dx1, DX2 = Ci * dx2;
    const float Q0  = Ci * q0,  Q1  = Ci * q1,  Q2  = Ci * q2;

    const float ws = pi0 * DX0 + pi1 * DX1 + pi2 * DX2;   // = sum K <pi,pj>
    const float cc = 2.0f * GAMMA_;
    atomicAdd(&out[3*i + 0], cc * fmaf(xt0, ws, -Q0));    // dmom (shift cancels)
    atomicAdd(&out[3*i + 1], cc * fmaf(xt1, ws, -Q1));
    atomicAdd(&out[3*i + 2], cc * fmaf(xt2, ws, -Q2));
    atomicAdd(&out[3*NPTS + 3*i + 0], DX0);               // dx
    atomicAdd(&out[3*NPTS + 3*i + 1], DX1);
    atomicAdd(&out[3*NPTS + 3*i + 2], DX2);
}

extern "C" void kernel_launch(void* const* d_in, const int* in_sizes, int n_in,
                              void* d_out, int out_size)
{
    const float* mom = (const float*)d_in[0];   // [1, 8192, 3]
    const float* x   = (const float*)d_in[1];   // [1, 8192, 3]
    float*       out = (float*)d_out;           // [2, 8192, 3] = dmom | dx

    zero_kernel<<<(out_size + 255) / 256, 256>>>(out, out_size);

    dim3 grid(NPTS / TILE, NSPLIT);             // (32, 32) = 1024 CTAs
    lddmm_kernel<<<grid, TILE>>>(mom, x, out);
}